// round 4
// baseline (speedup 1.0000x reference)
#include <cuda_runtime.h>
#include <cuda_bf16.h>
#include <cstdint>
#include <cstddef>

// ---------------------------------------------------------------------------
// ContrastiveLoss: loss = mean_i( log(sum_j exp(cos(o_i,t_j))) - cos(o_i,t_i) )
// B = 16384, D = 256, fp32 in, fp32 scalar out.
//
// compute_100 target (no tcgen05/wgmma) -> classic mma.sync pipeline, now FP8.
//   prep:  normalize rows in fp32, store e4m3 (cos == plain dot afterwards)
//   main:  fused 128x128x256 e4m3 GEMM tiles + exp-rowsum epilogue, 1 wave
//   final: deterministic reduction of 128 CTA partials
// ---------------------------------------------------------------------------

#define NROW   16384
#define DDIM   256
#define NTILES 128
#define NCTA   128

static __device__ __align__(16) uint8_t g_obf[NROW * DDIM]; // normalized e4m3
static __device__ __align__(16) uint8_t g_tbf[NROW * DDIM]; // normalized e4m3
static __device__ float g_partials[NCTA];

// SMEM layout (byte offsets). fp8 tile = 128 rows x 256 B = 32 KB.
#define OFF_A    0
#define OFF_B0   32768
#define OFF_B1   65536
#define OFF_RED  98304    // 4 x 128 floats
#define OFF_DW   100352   // 16 floats
#define SMEM_DYN 100416

// ---------------------------------------------------------------------------
__device__ __forceinline__ uint32_t smem_u32(const void* p) {
    uint32_t a;
    asm("{ .reg .u64 t; cvta.to.shared.u64 t, %1; cvt.u32.u64 %0, t; }"
        : "=r"(a) : "l"(p));
    return a;
}

__device__ __forceinline__ void cp16(uint32_t dst, const void* src) {
    asm volatile("cp.async.cg.shared.global [%0], [%1], 16;"
                 :: "r"(dst), "l"(src));
}
__device__ __forceinline__ void cp_commit() {
    asm volatile("cp.async.commit_group;" ::: "memory");
}
__device__ __forceinline__ void cp_wait0() {
    asm volatile("cp.async.wait_group 0;" ::: "memory");
}

__device__ __forceinline__ void ldm4(uint32_t* r, uint32_t addr) {
    asm volatile("ldmatrix.sync.aligned.m8n8.x4.shared.b16 {%0,%1,%2,%3}, [%4];"
                 : "=r"(r[0]), "=r"(r[1]), "=r"(r[2]), "=r"(r[3]) : "r"(addr));
}

// FP8 e4m3 MMA: D(16x8,f32) += A(16x32,e4m3) x B(32x8,e4m3)
__device__ __forceinline__ void mma16832(float* d, const uint32_t* a,
                                         uint32_t b0, uint32_t b1) {
    asm volatile(
        "mma.sync.aligned.m16n8k32.row.col.f32.e4m3.e4m3.f32 "
        "{%0,%1,%2,%3}, {%4,%5,%6,%7}, {%8,%9}, {%0,%1,%2,%3};"
        : "+f"(d[0]), "+f"(d[1]), "+f"(d[2]), "+f"(d[3])
        : "r"(a[0]), "r"(a[1]), "r"(a[2]), "r"(a[3]), "r"(b0), "r"(b1));
}

// Async-copy one 128x256B fp8 tile into swizzled SMEM. 256 threads x 8 chunks.
// Swizzle: 16B-chunk index c (0..15 within row) -> c ^ (row & 7).
__device__ __forceinline__ void tile_cp(const uint4* __restrict__ src,
                                        uint32_t dstbase, int tid) {
#pragma unroll
    for (int i = 0; i < 8; i++) {
        int c   = tid + (i << 8);
        int row = c >> 4, k16 = c & 15;
        uint32_t d = dstbase + (row << 8) + ((k16 ^ (row & 7)) << 4);
        cp16(d, src + c);
    }
}

// ---------------------------------------------------------------------------
// Kernel 1: fp32 row norms, write normalized e4m3. One block per row index.
// ---------------------------------------------------------------------------
__global__ void ContrastivePrep(const float* __restrict__ O,
                                const float* __restrict__ T) {
    __shared__ float red[8];
    int r = blockIdx.x, t = threadIdx.x;          // 128 threads, 2 elems each
    float2 a = ((const float2*)O)[(size_t)r * 128 + t];
    float2 b = ((const float2*)T)[(size_t)r * 128 + t];
    float so = a.x * a.x + a.y * a.y;
    float st = b.x * b.x + b.y * b.y;
#pragma unroll
    for (int s = 16; s; s >>= 1) {
        so += __shfl_xor_sync(0xffffffffu, so, s);
        st += __shfl_xor_sync(0xffffffffu, st, s);
    }
    if ((t & 31) == 0) { red[t >> 5] = so; red[4 + (t >> 5)] = st; }
    __syncthreads();
    float io = rsqrtf(red[0] + red[1] + red[2] + red[3]);
    float it = rsqrtf(red[4] + red[5] + red[6] + red[7]);
    uint16_t po, pt;
    asm("cvt.rn.satfinite.e4m3x2.f32 %0, %1, %2;"
        : "=h"(po) : "f"(a.y * io), "f"(a.x * io));   // high=arg1, low=arg2
    asm("cvt.rn.satfinite.e4m3x2.f32 %0, %1, %2;"
        : "=h"(pt) : "f"(b.y * it), "f"(b.x * it));
    ((uint16_t*)g_obf)[(size_t)r * 128 + t] = po;
    ((uint16_t*)g_tbf)[(size_t)r * 128 + t] = pt;
}

// ---------------------------------------------------------------------------
// Kernel 2: fused FP8 GEMM + exp rowsums. 128 CTAs x 256 threads (8 warps).
// Warp tile 64x32, warp grid 2x4 over the 128x128 CTA tile.
// ---------------------------------------------------------------------------
__global__ void __launch_bounds__(256, 1) ContrastiveMain() {
    extern __shared__ char smem[];
    const uint32_t sb = smem_u32(smem);
    const int tid  = threadIdx.x;
    const int lane = tid & 31, w = tid >> 5;
    const int wm = w >> 2, wn = w & 3;            // 2 x 4 warp grid
    const int g  = lane >> 2, t4 = lane & 3;
    const int cta = blockIdx.x;

    // ldmatrix.x4 per-lane addressing: lane l -> matrix l>>3, row l&7.
    // matrices: m0=(rows+0, chunk lo), m1=(rows+8, lo), m2=(rows+0, hi), m3=(rows+8, hi)
    const int lrow = ((lane >> 3) & 1) * 8 + (lane & 7);
    const int lhi  = lane >> 4;
    const int x7   = lane & 7;

    uint32_t aoff[4], boff[2];
#pragma unroll
    for (int mf = 0; mf < 4; mf++)
        aoff[mf] = sb + OFF_A + (uint32_t)((wm * 64 + mf * 16 + lrow) << 8);
#pragma unroll
    for (int p = 0; p < 2; p++)
        boff[p] = (uint32_t)((wn * 32 + p * 16 + lrow) << 8);

    // Prologue: A tile (resident) + first B tile
    tile_cp((const uint4*)g_obf + (size_t)cta * 2048, sb + OFF_A, tid);
    tile_cp((const uint4*)g_tbf, sb + OFF_B0, tid);
    cp_commit();
    cp_wait0();
    __syncthreads();

    float d[4][4][4];
#pragma unroll
    for (int mf = 0; mf < 4; mf++)
#pragma unroll
        for (int nf = 0; nf < 4; nf++)
#pragma unroll
            for (int r = 0; r < 4; r++) d[mf][nf][r] = 0.f;

    float sums[8];
#pragma unroll
    for (int s = 0; s < 8; s++) sums[s] = 0.f;
    float dsum = 0.f;

    for (int j = 0; j < NTILES; j++) {
        const uint32_t bbase = sb + ((j & 1) ? OFF_B1 : OFF_B0);
        if (j + 1 < NTILES) {
            tile_cp((const uint4*)g_tbf + (size_t)(j + 1) * 2048,
                    sb + ((j & 1) ? OFF_B0 : OFF_B1), tid);
            cp_commit();
        }

        // ---- K loop: 8 ksteps of k=32 (32B each) ----
#pragma unroll
        for (int ks = 0; ks < 8; ks++) {
            const uint32_t csel = (uint32_t)((((ks << 1) + lhi) ^ x7) << 4);
            uint32_t A[4][4], Bm[2][4];
#pragma unroll
            for (int mf = 0; mf < 4; mf++) ldm4(A[mf], aoff[mf] + csel);
#pragma unroll
            for (int p = 0; p < 2; p++)    ldm4(Bm[p], bbase + boff[p] + csel);
            // n16 block p: n8 sub0 frags = (m0, m2); sub1 = (m1, m3)
#pragma unroll
            for (int mf = 0; mf < 4; mf++)
#pragma unroll
                for (int p = 0; p < 2; p++) {
                    mma16832(d[mf][2 * p],     A[mf], Bm[p][0], Bm[p][2]);
                    mma16832(d[mf][2 * p + 1], A[mf], Bm[p][1], Bm[p][3]);
                }
        }

        // ---- epilogue: exp + per-row accumulate, capture diagonal ----
        const bool dt = (j == cta);
#pragma unroll
        for (int mf = 0; mf < 4; mf++)
#pragma unroll
            for (int h = 0; h < 2; h++) {
                float acc = 0.f;
#pragma unroll
                for (int nf = 0; nf < 4; nf++)
#pragma unroll
                    for (int rl = 0; rl < 2; rl++) {
                        float v = d[mf][nf][h * 2 + rl];
                        acc += __expf(v);
                        if (dt) {
                            int rloc = wm * 64 + mf * 16 + h * 8 + g;
                            int cloc = wn * 32 + nf * 8 + 2 * t4 + rl;
                            if (rloc == cloc) dsum += v;
                        }
                        d[mf][nf][h * 2 + rl] = 0.f;
                    }
                sums[mf * 2 + h] += acc;
            }

        if (j + 1 < NTILES) cp_wait0();
        __syncthreads();
    }

    // ---- reductions (deterministic) ----
#pragma unroll
    for (int s = 0; s < 8; s++) {
        sums[s] += __shfl_xor_sync(0xffffffffu, sums[s], 1);
        sums[s] += __shfl_xor_sync(0xffffffffu, sums[s], 2);
    }
#pragma unroll
    for (int off = 16; off; off >>= 1)
        dsum += __shfl_xor_sync(0xffffffffu, dsum, off);

    float* rp = (float*)(smem + OFF_RED);   // [4][128]: per wn-warp row sums
    float* dw = (float*)(smem + OFF_DW);    // [16]
    if (t4 == 0) {
#pragma unroll
        for (int s = 0; s < 8; s++) {
            int row = wm * 64 + (s >> 1) * 16 + (s & 1) * 8 + g;
            rp[wn * 128 + row] = sums[s];
        }
    }
    if (lane == 0) dw[w] = dsum;
    __syncthreads();

    if (tid < 128) {
        float srow = rp[tid] + rp[128 + tid] + rp[256 + tid] + rp[384 + tid];
        float li = __logf(srow);            // per-row log-sum-exp (max=0 safe)
#pragma unroll
        for (int off = 16; off; off >>= 1)
            li += __shfl_xor_sync(0xffffffffu, li, off);
        if (lane == 0) dw[8 + w] = li;
    }
    __syncthreads();

    if (tid == 0) {
        float tot = (dw[8] + dw[9] + dw[10] + dw[11])
                  - (dw[0] + dw[1] + dw[2] + dw[3]
                   + dw[4] + dw[5] + dw[6] + dw[7]);
        g_partials[cta] = tot;
    }
}

// ---------------------------------------------------------------------------
// Kernel 3: deterministic final reduction
// ---------------------------------------------------------------------------
__global__ void ContrastiveFinal(float* out) {
    __shared__ float red[128];
    int t = threadIdx.x;
    red[t] = g_partials[t];
    __syncthreads();
#pragma unroll
    for (int s = 64; s; s >>= 1) {
        if (t < s) red[t] += red[t + s];
        __syncthreads();
    }
    if (t == 0) out[0] = red[0] / (float)NROW;
}

// ---------------------------------------------------------------------------
extern "C" void kernel_launch(void* const* d_in, const int* in_sizes, int n_in,
                              void* d_out, int out_size) {
    const float* O = (const float*)d_in[0];
    const float* T = (const float*)d_in[1];
    cudaFuncSetAttribute(ContrastiveMain,
                         cudaFuncAttributeMaxDynamicSharedMemorySize, SMEM_DYN);
    ContrastivePrep<<<NROW, 128>>>(O, T);
    ContrastiveMain<<<NCTA, 256, SMEM_DYN>>>();
    ContrastiveFinal<<<1, 128>>>((float*)d_out);
}

// round 5
// speedup vs baseline: 1.0772x; 1.0772x over previous
#include <cuda_runtime.h>
#include <cuda_bf16.h>
#include <cstdint>
#include <cstddef>

// ---------------------------------------------------------------------------
// ContrastiveLoss: loss = mean_i( log(sum_j exp(cos(o_i,t_j))) - cos(o_i,t_i) )
// B = 16384, D = 256, fp32 in, fp32 scalar out.
//
// bf16 mma.sync pipeline (fp8 legacy path measured SLOWER on sm_100 -> bf16).
//   prep:  normalize rows fp32 -> bf16; also emits diag_i = <o_i,t_i> directly
//   main:  128x64 tiles, double-buffered accumulators: epilogue (exp/accum) of
//          tile j-1 interleaved into the K-loop of tile j -> MUFU hides under
//          the tensor pipe. 128 CTAs x 256 threads, one wave.
//   final: deterministic reduction (128 logZ partials + 16384 diag terms)
// ---------------------------------------------------------------------------

#define NROW   16384
#define DDIM   256
#define NT     64              // tile N
#define NTILES (NROW / NT)     // 256
#define NCTA   128

static __device__ __align__(16) __nv_bfloat16 g_obf[NROW * DDIM];
static __device__ __align__(16) __nv_bfloat16 g_tbf[NROW * DDIM];
static __device__ float g_diag[NROW];
static __device__ float g_partials[NCTA];

// SMEM layout. A tile 128x512B = 64KB resident; B tiles 64x512B = 32KB x2.
#define OFF_A    0
#define OFF_B0   65536
#define OFF_B1   98304
#define OFF_RED  131072   // 4 x 128 floats
#define OFF_DW   133120   // 4 floats
#define SMEM_DYN 133184

// ---------------------------------------------------------------------------
__device__ __forceinline__ uint32_t smem_u32(const void* p) {
    uint32_t a;
    asm("{ .reg .u64 t; cvta.to.shared.u64 t, %1; cvt.u32.u64 %0, t; }"
        : "=r"(a) : "l"(p));
    return a;
}
__device__ __forceinline__ void cp16(uint32_t dst, const void* src) {
    asm volatile("cp.async.cg.shared.global [%0], [%1], 16;" :: "r"(dst), "l"(src));
}
__device__ __forceinline__ void cp_commit() {
    asm volatile("cp.async.commit_group;" ::: "memory");
}
__device__ __forceinline__ void cp_wait0() {
    asm volatile("cp.async.wait_group 0;" ::: "memory");
}
__device__ __forceinline__ void ldm4(uint32_t* r, uint32_t addr) {
    asm volatile("ldmatrix.sync.aligned.m8n8.x4.shared.b16 {%0,%1,%2,%3}, [%4];"
                 : "=r"(r[0]), "=r"(r[1]), "=r"(r[2]), "=r"(r[3]) : "r"(addr));
}
__device__ __forceinline__ void mma16816(float* d, const uint32_t* a,
                                         uint32_t b0, uint32_t b1) {
    asm volatile(
        "mma.sync.aligned.m16n8k16.row.col.f32.bf16.bf16.f32 "
        "{%0,%1,%2,%3}, {%4,%5,%6,%7}, {%8,%9}, {%0,%1,%2,%3};"
        : "+f"(d[0]), "+f"(d[1]), "+f"(d[2]), "+f"(d[3])
        : "r"(a[0]), "r"(a[1]), "r"(a[2]), "r"(a[3]), "r"(b0), "r"(b1));
}

// B-tile copy: 64 rows x 512B = 32KB, 256 threads x 8 chunks, swizzled.
__device__ __forceinline__ void tile_cp_b(const uint4* __restrict__ src,
                                          uint32_t dstbase, int tid) {
#pragma unroll
    for (int i = 0; i < 8; i++) {
        int c   = tid + (i << 8);
        int row = c >> 5, k16 = c & 31;
        cp16(dstbase + (row << 9) + ((k16 ^ (row & 7)) << 4), src + c);
    }
}
// A-tile copy: 128 rows x 512B = 64KB, 256 threads x 16 chunks.
__device__ __forceinline__ void tile_cp_a(const uint4* __restrict__ src,
                                          uint32_t dstbase, int tid) {
#pragma unroll
    for (int i = 0; i < 16; i++) {
        int c   = tid + (i << 8);
        int row = c >> 5, k16 = c & 31;
        cp16(dstbase + (row << 9) + ((k16 ^ (row & 7)) << 4), src + c);
    }
}

// ---------------------------------------------------------------------------
// Kernel 1: fp32 row norms -> normalized bf16, plus diag dot product.
// ---------------------------------------------------------------------------
__global__ void ContrastivePrep(const float* __restrict__ O,
                                const float* __restrict__ T) {
    __shared__ float red[12];
    int r = blockIdx.x, t = threadIdx.x;          // 128 threads, 2 elems each
    float2 a = ((const float2*)O)[(size_t)r * 128 + t];
    float2 b = ((const float2*)T)[(size_t)r * 128 + t];
    float so = a.x * a.x + a.y * a.y;
    float st = b.x * b.x + b.y * b.y;
#pragma unroll
    for (int s = 16; s; s >>= 1) {
        so += __shfl_xor_sync(0xffffffffu, so, s);
        st += __shfl_xor_sync(0xffffffffu, st, s);
    }
    if ((t & 31) == 0) { red[t >> 5] = so; red[4 + (t >> 5)] = st; }
    __syncthreads();
    float io = rsqrtf(red[0] + red[1] + red[2] + red[3]);
    float it = rsqrtf(red[4] + red[5] + red[6] + red[7]);
    __nv_bfloat162 oa = __floats2bfloat162_rn(a.x * io, a.y * io);
    __nv_bfloat162 tb = __floats2bfloat162_rn(b.x * it, b.y * it);
    ((__nv_bfloat162*)g_obf)[(size_t)r * 128 + t] = oa;
    ((__nv_bfloat162*)g_tbf)[(size_t)r * 128 + t] = tb;
    float dp = __bfloat162float(oa.x) * __bfloat162float(tb.x)
             + __bfloat162float(oa.y) * __bfloat162float(tb.y);
#pragma unroll
    for (int s = 16; s; s >>= 1) dp += __shfl_xor_sync(0xffffffffu, dp, s);
    if ((t & 31) == 0) red[8 + (t >> 5)] = dp;
    __syncthreads();
    if (t == 0) g_diag[r] = red[8] + red[9] + red[10] + red[11];
}

// ---------------------------------------------------------------------------
// Kernel 2: fused GEMM + exp rowsums. 128 CTAs x 256 threads (8 warps).
// Warp tile 64x16 (2x4 warp grid over 128x64). Accum sets d0/d1 ping-pong:
// tile j accumulates into set (j&1) while the epilogue of tile j-1 runs on
// the other set, interleaved 2 elements per k-step.
// ---------------------------------------------------------------------------

// DC: accumulate set for this tile; DE: set being epilogued (tile j-1).
#define TILE_BODY(DC, DE, BOFFS, EPI)                                        \
    do {                                                                     \
        const uint32_t bbase_ = sb + (BOFFS);                                \
        _Pragma("unroll")                                                    \
        for (int ks = 0; ks < 16; ks++) {                                    \
            const uint32_t csel = (uint32_t)((((ks << 1) + lhi) ^ x7) << 4); \
            uint32_t A4[4][4], Bm[4];                                        \
            _Pragma("unroll")                                                \
            for (int mf = 0; mf < 4; mf++) ldm4(A4[mf], aoff[mf] + csel);    \
            ldm4(Bm, bbase_ + boff + csel);                                  \
            _Pragma("unroll")                                                \
            for (int mf = 0; mf < 4; mf++) {                                 \
                mma16816(DC[mf][0], A4[mf], Bm[0], Bm[2]);                   \
                mma16816(DC[mf][1], A4[mf], Bm[1], Bm[3]);                   \
            }                                                                \
            if (EPI) {                                                       \
                _Pragma("unroll")                                            \
                for (int i = 0; i < 2; i++) {                                \
                    const int e = 2 * ks + i;                                \
                    const int mf = e >> 3, nf = (e >> 2) & 1, r = e & 3;     \
                    float v = DE[mf][nf][r];                                 \
                    DE[mf][nf][r] = 0.f;                                     \
                    sums[mf * 2 + (r >> 1)] += __expf(v);                    \
                }                                                            \
            }                                                                \
        }                                                                    \
    } while (0)

__global__ void __launch_bounds__(256, 1) ContrastiveMain() {
    extern __shared__ char smem[];
    const uint32_t sb = smem_u32(smem);
    const int tid  = threadIdx.x;
    const int lane = tid & 31, w = tid >> 5;
    const int wm = w >> 2, wn = w & 3;            // 2 x 4 warp grid
    const int g  = lane >> 2;
    const int cta = blockIdx.x;

    const int lrow = ((lane >> 3) & 1) * 8 + (lane & 7);
    const int lhi  = lane >> 4;
    const int x7   = lane & 7;

    uint32_t aoff[4];
#pragma unroll
    for (int mf = 0; mf < 4; mf++)
        aoff[mf] = sb + OFF_A + (uint32_t)((wm * 64 + mf * 16 + lrow) << 9);
    const uint32_t boff = (uint32_t)((wn * 16 + lrow) << 9);

    // Prologue: resident A + B(0)
    tile_cp_a((const uint4*)g_obf + (size_t)cta * 4096, sb + OFF_A, tid);
    tile_cp_b((const uint4*)g_tbf, sb + OFF_B0, tid);
    cp_commit();
    cp_wait0();
    __syncthreads();

    float d0[4][2][4], d1[4][2][4];
#pragma unroll
    for (int mf = 0; mf < 4; mf++)
#pragma unroll
        for (int nf = 0; nf < 2; nf++)
#pragma unroll
            for (int r = 0; r < 4; r++) { d0[mf][nf][r] = 0.f; d1[mf][nf][r] = 0.f; }

    float sums[8];
#pragma unroll
    for (int s = 0; s < 8; s++) sums[s] = 0.f;

    // Tile 0 (set d0, no epilogue yet); prefetch B(1)
    tile_cp_b((const uint4*)g_tbf + 2048, sb + OFF_B1, tid);
    cp_commit();
    TILE_BODY(d0, d1, OFF_B0, false);
    cp_wait0();
    __syncthreads();

    // Tiles 1..254 in pairs
    for (int jp = 0; jp < 127; jp++) {
        // tile 2jp+1 (set d1, epi d0); prefetch B(2jp+2) -> B0
        tile_cp_b((const uint4*)g_tbf + (size_t)(2 * jp + 2) * 2048,
                  sb + OFF_B0, tid);
        cp_commit();
        TILE_BODY(d1, d0, OFF_B1, true);
        cp_wait0();
        __syncthreads();
        // tile 2jp+2 (set d0, epi d1); prefetch B(2jp+3) -> B1
        tile_cp_b((const uint4*)g_tbf + (size_t)(2 * jp + 3) * 2048,
                  sb + OFF_B1, tid);
        cp_commit();
        TILE_BODY(d0, d1, OFF_B0, true);
        cp_wait0();
        __syncthreads();
    }

    // Tile 255 (set d1, epi d0), then tail epilogue of d1
    TILE_BODY(d1, d0, OFF_B1, true);
#pragma unroll
    for (int e = 0; e < 32; e++) {
        const int mf = e >> 3, nf = (e >> 2) & 1, r = e & 3;
        sums[mf * 2 + (r >> 1)] += __expf(d1[mf][nf][r]);
    }

    // ---- reductions (deterministic) ----
#pragma unroll
    for (int s = 0; s < 8; s++) {
        sums[s] += __shfl_xor_sync(0xffffffffu, sums[s], 1);
        sums[s] += __shfl_xor_sync(0xffffffffu, sums[s], 2);
    }
    float* rp = (float*)(smem + OFF_RED);   // [4][128]
    float* dw = (float*)(smem + OFF_DW);    // [4]
    if ((lane & 3) == 0) {
#pragma unroll
        for (int s = 0; s < 8; s++) {
            int row = wm * 64 + (s >> 1) * 16 + (s & 1) * 8 + g;
            rp[wn * 128 + row] = sums[s];
        }
    }
    __syncthreads();
    if (tid < 128) {
        float srow = rp[tid] + rp[128 + tid] + rp[256 + tid] + rp[384 + tid];
        float li = __logf(srow);
#pragma unroll
        for (int off = 16; off; off >>= 1)
            li += __shfl_xor_sync(0xffffffffu, li, off);
        if (lane == 0) dw[w] = li;
    }
    __syncthreads();
    if (tid == 0) g_partials[cta] = dw[0] + dw[1] + dw[2] + dw[3];
}

// ---------------------------------------------------------------------------
// Kernel 3: deterministic final reduction: mean(logZ) - mean(diag)
// ---------------------------------------------------------------------------
__global__ void ContrastiveFinal(float* out) {
    __shared__ float red[256];
    int t = threadIdx.x;
    float s = 0.f;
    for (int i = t; i < NROW; i += 256) s -= g_diag[i];
    if (t < NCTA) s += g_partials[t];
    red[t] = s;
    __syncthreads();
#pragma unroll
    for (int k = 128; k; k >>= 1) {
        if (t < k) red[t] += red[t + k];
        __syncthreads();
    }
    if (t == 0) out[0] = red[0] / (float)NROW;
}

// ---------------------------------------------------------------------------
extern "C" void kernel_launch(void* const* d_in, const int* in_sizes, int n_in,
                              void* d_out, int out_size) {
    const float* O = (const float*)d_in[0];
    const float* T = (const float*)d_in[1];
    cudaFuncSetAttribute(ContrastiveMain,
                         cudaFuncAttributeMaxDynamicSharedMemorySize, SMEM_DYN);
    ContrastivePrep<<<NROW, 128>>>(O, T);
    ContrastiveMain<<<NCTA, 256, SMEM_DYN>>>();
    ContrastiveFinal<<<1, 256>>>((float*)d_out);
}

// round 6
// speedup vs baseline: 1.1042x; 1.0251x over previous
#include <cuda_runtime.h>
#include <cuda_bf16.h>
#include <cstdint>
#include <cstddef>

// ---------------------------------------------------------------------------
// ContrastiveLoss: loss = mean_i( log(sum_j exp(cos(o_i,t_j))) - cos(o_i,t_i) )
// B = 16384, D = 256, fp32 in, fp32 scalar out.
//
// bf16 mma.sync pipeline, 512 threads (4 warps/SMSP) for issue overlap.
//   prep:  normalize rows fp32 -> bf16; emits diag_i = <o_i,t_i> directly
//   main:  128x128x256 tiles, warp tile 32x32 (4x4 grid), phase epilogue;
//          cross-warp overlap hides LDSM/MUFU under the tensor pipe. 1 wave.
//   final: deterministic reduction (128 logZ partials + 16384 diag terms)
// ---------------------------------------------------------------------------

#define NROW   16384
#define DDIM   256
#define NTILES 128
#define NCTA   128

static __device__ __align__(16) __nv_bfloat16 g_obf[NROW * DDIM];
static __device__ __align__(16) __nv_bfloat16 g_tbf[NROW * DDIM];
static __device__ float g_diag[NROW];
static __device__ float g_partials[NCTA];

// SMEM layout: A 64KB resident, B0/B1 64KB each, reduction scratch.
#define OFF_A    0
#define OFF_B0   65536
#define OFF_B1   131072
#define OFF_RED  196608   // 4 x 128 floats
#define OFF_DW   198656   // 4 floats
#define SMEM_DYN 198720

// ---------------------------------------------------------------------------
__device__ __forceinline__ uint32_t smem_u32(const void* p) {
    uint32_t a;
    asm("{ .reg .u64 t; cvta.to.shared.u64 t, %1; cvt.u32.u64 %0, t; }"
        : "=r"(a) : "l"(p));
    return a;
}
__device__ __forceinline__ void cp16(uint32_t dst, const void* src) {
    asm volatile("cp.async.cg.shared.global [%0], [%1], 16;" :: "r"(dst), "l"(src));
}
__device__ __forceinline__ void cp_commit() {
    asm volatile("cp.async.commit_group;" ::: "memory");
}
__device__ __forceinline__ void cp_wait0() {
    asm volatile("cp.async.wait_group 0;" ::: "memory");
}
__device__ __forceinline__ void ldm4(uint32_t* r, uint32_t addr) {
    asm volatile("ldmatrix.sync.aligned.m8n8.x4.shared.b16 {%0,%1,%2,%3}, [%4];"
                 : "=r"(r[0]), "=r"(r[1]), "=r"(r[2]), "=r"(r[3]) : "r"(addr));
}
__device__ __forceinline__ void mma16816(float* d, const uint32_t* a,
                                         uint32_t b0, uint32_t b1) {
    asm volatile(
        "mma.sync.aligned.m16n8k16.row.col.f32.bf16.bf16.f32 "
        "{%0,%1,%2,%3}, {%4,%5,%6,%7}, {%8,%9}, {%0,%1,%2,%3};"
        : "+f"(d[0]), "+f"(d[1]), "+f"(d[2]), "+f"(d[3])
        : "r"(a[0]), "r"(a[1]), "r"(a[2]), "r"(a[3]), "r"(b0), "r"(b1));
}

// Copy one 128x256 bf16 tile (64KB) into swizzled SMEM. 512 threads x 8 chunks.
__device__ __forceinline__ void tile_cp(const uint4* __restrict__ src,
                                        uint32_t dstbase, int tid) {
#pragma unroll
    for (int i = 0; i < 8; i++) {
        int c   = tid + (i << 9);
        int row = c >> 5, k16 = c & 31;
        cp16(dstbase + (row << 9) + ((k16 ^ (row & 7)) << 4), src + c);
    }
}

// ---------------------------------------------------------------------------
// Kernel 1: fp32 row norms -> normalized bf16, plus diag dot product.
// ---------------------------------------------------------------------------
__global__ void ContrastivePrep(const float* __restrict__ O,
                                const float* __restrict__ T) {
    __shared__ float red[12];
    int r = blockIdx.x, t = threadIdx.x;          // 128 threads, 2 elems each
    float2 a = ((const float2*)O)[(size_t)r * 128 + t];
    float2 b = ((const float2*)T)[(size_t)r * 128 + t];
    float so = a.x * a.x + a.y * a.y;
    float st = b.x * b.x + b.y * b.y;
#pragma unroll
    for (int s = 16; s; s >>= 1) {
        so += __shfl_xor_sync(0xffffffffu, so, s);
        st += __shfl_xor_sync(0xffffffffu, st, s);
    }
    if ((t & 31) == 0) { red[t >> 5] = so; red[4 + (t >> 5)] = st; }
    __syncthreads();
    float io = rsqrtf(red[0] + red[1] + red[2] + red[3]);
    float it = rsqrtf(red[4] + red[5] + red[6] + red[7]);
    __nv_bfloat162 oa = __floats2bfloat162_rn(a.x * io, a.y * io);
    __nv_bfloat162 tb = __floats2bfloat162_rn(b.x * it, b.y * it);
    ((__nv_bfloat162*)g_obf)[(size_t)r * 128 + t] = oa;
    ((__nv_bfloat162*)g_tbf)[(size_t)r * 128 + t] = tb;
    float dp = __bfloat162float(oa.x) * __bfloat162float(tb.x)
             + __bfloat162float(oa.y) * __bfloat162float(tb.y);
#pragma unroll
    for (int s = 16; s; s >>= 1) dp += __shfl_xor_sync(0xffffffffu, dp, s);
    if ((t & 31) == 0) red[8 + (t >> 5)] = dp;
    __syncthreads();
    if (t == 0) g_diag[r] = red[8] + red[9] + red[10] + red[11];
}

// ---------------------------------------------------------------------------
// Kernel 2: fused GEMM + exp rowsums. 128 CTAs x 512 threads (16 warps).
// Warp tile 32x32, warp grid 4x4 over the 128x128 CTA tile.
// ---------------------------------------------------------------------------
__global__ void __launch_bounds__(512, 1) ContrastiveMain() {
    extern __shared__ char smem[];
    const uint32_t sb = smem_u32(smem);
    const int tid  = threadIdx.x;
    const int lane = tid & 31, w = tid >> 5;
    const int wm = w >> 2, wn = w & 3;            // 4 x 4 warp grid
    const int g  = lane >> 2;
    const int cta = blockIdx.x;

    const int lrow = ((lane >> 3) & 1) * 8 + (lane & 7);
    const int lhi  = lane >> 4;
    const int x7   = lane & 7;

    uint32_t aoff[2], boff[2];
#pragma unroll
    for (int mf = 0; mf < 2; mf++)
        aoff[mf] = sb + OFF_A + (uint32_t)((wm * 32 + mf * 16 + lrow) << 9);
#pragma unroll
    for (int p = 0; p < 2; p++)
        boff[p] = (uint32_t)((wn * 32 + p * 16 + lrow) << 9);

    // Prologue: resident A + first B tile
    tile_cp((const uint4*)g_obf + (size_t)cta * 4096, sb + OFF_A, tid);
    tile_cp((const uint4*)g_tbf, sb + OFF_B0, tid);
    cp_commit();
    cp_wait0();
    __syncthreads();

    float d[2][4][4];
#pragma unroll
    for (int mf = 0; mf < 2; mf++)
#pragma unroll
        for (int nf = 0; nf < 4; nf++)
#pragma unroll
            for (int r = 0; r < 4; r++) d[mf][nf][r] = 0.f;

    float sums[4];
#pragma unroll
    for (int s = 0; s < 4; s++) sums[s] = 0.f;

    for (int j = 0; j < NTILES; j++) {
        const uint32_t bbase = sb + ((j & 1) ? OFF_B1 : OFF_B0);
        if (j + 1 < NTILES) {
            tile_cp((const uint4*)g_tbf + (size_t)(j + 1) * 4096,
                    sb + ((j & 1) ? OFF_B0 : OFF_B1), tid);
            cp_commit();
        }

        // ---- K loop: 16 ksteps of k=16 ----
#pragma unroll
        for (int ks = 0; ks < 16; ks++) {
            const uint32_t csel = (uint32_t)((((ks << 1) + lhi) ^ x7) << 4);
            uint32_t A2[2][4], Bm[2][4];
#pragma unroll
            for (int mf = 0; mf < 2; mf++) ldm4(A2[mf], aoff[mf] + csel);
#pragma unroll
            for (int p = 0; p < 2; p++)    ldm4(Bm[p], bbase + boff[p] + csel);
#pragma unroll
            for (int mf = 0; mf < 2; mf++)
#pragma unroll
                for (int p = 0; p < 2; p++) {
                    mma16816(d[mf][2 * p],     A2[mf], Bm[p][0], Bm[p][2]);
                    mma16816(d[mf][2 * p + 1], A2[mf], Bm[p][1], Bm[p][3]);
                }
        }

        // ---- epilogue: exp + per-row accumulate ----
#pragma unroll
        for (int mf = 0; mf < 2; mf++)
#pragma unroll
            for (int h = 0; h < 2; h++) {
                float acc = 0.f;
#pragma unroll
                for (int nf = 0; nf < 4; nf++)
#pragma unroll
                    for (int rl = 0; rl < 2; rl++) {
                        acc += __expf(d[mf][nf][h * 2 + rl]);
                        d[mf][nf][h * 2 + rl] = 0.f;
                    }
                sums[mf * 2 + h] += acc;
            }

        if (j + 1 < NTILES) cp_wait0();
        __syncthreads();
    }

    // ---- reductions (deterministic) ----
#pragma unroll
    for (int s = 0; s < 4; s++) {
        sums[s] += __shfl_xor_sync(0xffffffffu, sums[s], 1);
        sums[s] += __shfl_xor_sync(0xffffffffu, sums[s], 2);
    }
    float* rp = (float*)(smem + OFF_RED);   // [4][128]: per wn column-block
    float* dw = (float*)(smem + OFF_DW);    // [4]
    if ((lane & 3) == 0) {
#pragma unroll
        for (int s = 0; s < 4; s++) {
            int row = wm * 32 + (s >> 1) * 16 + (s & 1) * 8 + g;
            rp[wn * 128 + row] = sums[s];
        }
    }
    __syncthreads();
    if (tid < 128) {
        float srow = rp[tid] + rp[128 + tid] + rp[256 + tid] + rp[384 + tid];
        float li = __logf(srow);            // per-row log-sum-exp (max=0 safe)
#pragma unroll
        for (int off = 16; off; off >>= 1)
            li += __shfl_xor_sync(0xffffffffu, li, off);
        if (lane == 0) dw[w] = li;
    }
    __syncthreads();
    if (tid == 0) g_partials[cta] = dw[0] + dw[1] + dw[2] + dw[3];
}

// ---------------------------------------------------------------------------
// Kernel 3: deterministic final reduction: mean(logZ) - mean(diag)
// ---------------------------------------------------------------------------
__global__ void ContrastiveFinal(float* out) {
    __shared__ float red[256];
    int t = threadIdx.x;
    float s = 0.f;
    for (int i = t; i < NROW; i += 256) s -= g_diag[i];
    if (t < NCTA) s += g_partials[t];
    red[t] = s;
    __syncthreads();
#pragma unroll
    for (int k = 128; k; k >>= 1) {
        if (t < k) red[t] += red[t + k];
        __syncthreads();
    }
    if (t == 0) out[0] = red[0] / (float)NROW;
}

// ---------------------------------------------------------------------------
extern "C" void kernel_launch(void* const* d_in, const int* in_sizes, int n_in,
                              void* d_out, int out_size) {
    const float* O = (const float*)d_in[0];
    const float* T = (const float*)d_in[1];
    cudaFuncSetAttribute(ContrastiveMain,
                         cudaFuncAttributeMaxDynamicSharedMemorySize, SMEM_DYN);
    ContrastivePrep<<<NROW, 128>>>(O, T);
    ContrastiveMain<<<NCTA, 512, SMEM_DYN>>>();
    ContrastiveFinal<<<1, 256>>>((float*)d_out);
}